// round 13
// baseline (speedup 1.0000x reference)
#include <cuda_runtime.h>
#include <cuda_bf16.h>
#include <cstdint>

// Problem constants (fixed by the dataset)
#define NN 65536
#define EE 131072
#define EPS_LN 1e-5f
#define SCALE_ATT 0.25f   // HD^-0.5, HD=16

// ---------------- scratch (device globals; no allocation allowed) ------------
__device__ float g_QKa[(size_t)NN * 512];   // [K1 | Q2] from x_a
__device__ float g_QKb[(size_t)NN * 512];   // [Q1 | K2] from x_b
__device__ float g_Sa[(size_t)NN * 128];    // scatter target for pass2 (out_a)
__device__ float g_Sb[(size_t)NN * 128];    // scatter target for pass1 (out_b)
__device__ __nv_bfloat16 g_Xh[(size_t)2 * NN * 256];  // bf16 hi of x_a|x_b
__device__ __nv_bfloat16 g_Xl[(size_t)2 * NN * 256];  // bf16 residual
__device__ __nv_bfloat16 g_Mh[2 * 512 * 256];         // combined QK weights hi
__device__ __nv_bfloat16 g_Ml[2 * 512 * 256];         // combined QK weights lo
__device__ float g_bM[2 * 512];
__device__ float g_u1[4 * 64], g_w1[4 * 64];
__device__ float g_u2[4 * 64], g_w2[4 * 64];
__device__ float g_Ta[256 * 256], g_Tb[256 * 256];  // Wo @ BD(Wout)
__device__ float g_M2a[256 * 128], g_M2b[256 * 128];
__device__ float g_vba[256], g_vbb[256];

__device__ __forceinline__ uint32_t smem_to_u32(const void* p) {
    uint32_t a;
    asm("{ .reg .u64 t; cvta.to.shared.u64 t, %1; cvt.u32.u64 %0, t; }" : "=r"(a) : "l"(p));
    return a;
}

// ---------------- zero the scatter accumulators ------------------------------
__global__ void clear_S() {
    int i = blockIdx.x * blockDim.x + threadIdx.x;
    int stride = gridDim.x * blockDim.x;
    float4 z = make_float4(0.f, 0.f, 0.f, 0.f);
    float4* A = reinterpret_cast<float4*>(g_Sa);
    float4* B = reinterpret_cast<float4*>(g_Sb);
    const int total = NN * 128 / 4;
    for (int t = i; t < total; t += stride) { A[t] = z; B[t] = z; }
}

// ---------------- convert X to bf16 hi/lo ------------------------------------
__global__ void convert_X(const float* __restrict__ xa, const float* __restrict__ xb) {
    int side = blockIdx.y;
    const float* X = side ? xb : xa;
    size_t i = (size_t)blockIdx.x * blockDim.x + threadIdx.x;  // group of 4 floats
    const size_t total = (size_t)NN * 256 / 4;
    if (i >= total) return;
    float4 v = reinterpret_cast<const float4*>(X)[i];
    __nv_bfloat16 h0 = __float2bfloat16(v.x), h1 = __float2bfloat16(v.y);
    __nv_bfloat16 h2 = __float2bfloat16(v.z), h3 = __float2bfloat16(v.w);
    __nv_bfloat16 l0 = __float2bfloat16(v.x - __bfloat162float(h0));
    __nv_bfloat16 l1 = __float2bfloat16(v.y - __bfloat162float(h1));
    __nv_bfloat16 l2 = __float2bfloat16(v.z - __bfloat162float(h2));
    __nv_bfloat16 l3 = __float2bfloat16(v.w - __bfloat162float(h3));
    __nv_bfloat162* H = reinterpret_cast<__nv_bfloat162*>(g_Xh + (size_t)side * NN * 256);
    __nv_bfloat162* L = reinterpret_cast<__nv_bfloat162*>(g_Xl + (size_t)side * NN * 256);
    H[i * 2]     = __nv_bfloat162(h0, h1);
    H[i * 2 + 1] = __nv_bfloat162(h2, h3);
    L[i * 2]     = __nv_bfloat162(l0, l1);
    L[i * 2 + 1] = __nv_bfloat162(l2, l3);
}

// ---------------- combined QK weight precompute (bf16 hi/lo output) ----------
__global__ void combine_qk(int side,
                           const float* __restrict__ Wn, const float* __restrict__ bn,
                           const float* __restrict__ Wf, const float* __restrict__ bf,
                           const float* __restrict__ Ws, const float* __restrict__ bs) {
    __nv_bfloat16* Mh = g_Mh + side * 512 * 256;
    __nv_bfloat16* Ml = g_Ml + side * 512 * 256;
    float* bias = g_bM + side * 512;
    int idx = blockIdx.x * blockDim.x + threadIdx.x;  // 512*256 threads
    int jout = idx >> 8;        // 0..511
    int c    = idx & 255;
    int hsel = jout >> 8;
    int jo   = jout & 255;
    int g = jo >> 6, j = jo & 63;
    const float* Wsub = hsel ? Ws : Wf;
    float acc = 0.f;
#pragma unroll 8
    for (int d = 0; d < 64; d++)
        acc += Wsub[j * 64 + d] * Wn[(g * 64 + d) * 256 + c];
    __nv_bfloat16 h = __float2bfloat16(acc);
    Mh[jout * 256 + c] = h;
    Ml[jout * 256 + c] = __float2bfloat16(acc - __bfloat162float(h));
    if (c == 0) {
        const float* bsub = hsel ? bs : bf;
        float bacc = bsub[j];
#pragma unroll 8
        for (int d = 0; d < 64; d++) bacc += Wsub[j * 64 + d] * bn[g * 64 + d];
        bias[jout] = bacc;
    }
}

// ---------------- u/w precompute ---------------------------------------------
__global__ void compute_uw(int pass, const float* __restrict__ Win,
                           const float* __restrict__ bin,
                           const float* __restrict__ We, const float* __restrict__ be) {
    float* u = pass ? g_u2 : g_u1;
    float* w = pass ? g_w2 : g_w1;
    int t = threadIdx.x;
    int ki = t >> 6, j = t & 63;
    const float* Wv = Win + 128 * 64;
    float su = 0.f, sw = 0.f;
#pragma unroll 8
    for (int d = 0; d < 64; d++) {
        float wv = Wv[j * 64 + d];
        su += wv * We[ki * 64 + d];
        sw += wv * be[ki * 64 + d];
    }
    u[t] = su;
    w[t] = sw + bin[128 + j];
}

// ---------------- T = Wo @ BD(Wout) ------------------------------------------
__global__ void compute_T(int side, const float* __restrict__ Wo,
                          const float* __restrict__ Wout) {
    float* T = side ? g_Tb : g_Ta;
    int idx = blockIdx.x * 256 + threadIdx.x;
    int r = idx >> 8, qo = idx & 255;
    int qi = qo >> 6, j = qo & 63;
    float acc = 0.f;
#pragma unroll 8
    for (int jj = 0; jj < 64; jj++)
        acc += Wo[r * 256 + qi * 64 + jj] * Wout[jj * 64 + j];
    T[idx] = acc;
}

// ---------------- M2 = T @ G(u,w) --------------------------------------------
__global__ void compute_M2(int side, const float* __restrict__ Wo,
                           const float* __restrict__ bout) {
    const float* T = side ? g_Tb : g_Ta;
    const float* u = side ? g_u1 : g_u2;
    const float* w = side ? g_w1 : g_w2;
    float* M2 = side ? g_M2b : g_M2a;
    float* vb = side ? g_vbb : g_vba;
    int idx = blockIdx.x * 256 + threadIdx.x;
    int r = idx >> 7, s = idx & 127;
    int z = s >> 6;
    int rest = s & 63;
    int h = rest >> 4, qr = (rest >> 2) & 3, ki = rest & 3;
    const float* coef = z ? u : w;
    float acc = 0.f;
#pragma unroll
    for (int hd = 0; hd < 16; hd++)
        acc += T[r * 256 + qr * 64 + h * 16 + hd] * coef[ki * 64 + h * 16 + hd];
    M2[r * 128 + s] = acc;
    if (s == 0) {
        float b = 0.f;
        for (int qi2 = 0; qi2 < 4; qi2++)
#pragma unroll 8
            for (int jj = 0; jj < 64; jj++)
                b += Wo[r * 256 + qi2 * 64 + jj] * bout[jj];
        vb[r] = b;
    }
}

// ---------------- mma.sync QK GEMM (cp.async double-buffered) ----------------
// out[N,512] = X[N,256] @ M^T + bias, split-bf16 3-term, fp32 accum.
// Block: 256 threads (8 warps, 4m x 2n), tile 128M x 128N, K in 4 chunks of 64.
// grid: (4 nc, N/128 rows, 2 sides) — nc fastest for L2 reuse of A.
#define SROW 72                              // padded bf16 stride (conflict-free)
#define MAT_BYTES (128 * SROW * 2)           // 18432 B per matrix tile
#define STAGE_BYTES (4 * MAT_BYTES)          // 73728 B per stage
#define GEMM_SMEM (2 * STAGE_BYTES)          // 147456 B (double buffer)

#define LDSM_X4(r, addr) \
    asm volatile("ldmatrix.sync.aligned.m8n8.x4.shared.b16 {%0,%1,%2,%3}, [%4];" \
        : "=r"((r)[0]), "=r"((r)[1]), "=r"((r)[2]), "=r"((r)[3]) : "r"(addr))
#define LDSM_X2(r, addr) \
    asm volatile("ldmatrix.sync.aligned.m8n8.x2.shared.b16 {%0,%1}, [%2];" \
        : "=r"((r)[0]), "=r"((r)[1]) : "r"(addr))
#define MMA16816(c, a, b) \
    asm volatile("mma.sync.aligned.m16n8k16.row.col.f32.bf16.bf16.f32 " \
        "{%0,%1,%2,%3}, {%4,%5,%6,%7}, {%8,%9}, {%0,%1,%2,%3};" \
        : "+f"((c)[0]), "+f"((c)[1]), "+f"((c)[2]), "+f"((c)[3]) \
        : "r"((a)[0]), "r"((a)[1]), "r"((a)[2]), "r"((a)[3]), "r"((b)[0]), "r"((b)[1]))
#define CP_ASYNC16(dst, src) \
    asm volatile("cp.async.cg.shared.global [%0], [%1], 16;" :: "r"(dst), "l"(src) : "memory")
#define CP_COMMIT() asm volatile("cp.async.commit_group;" ::: "memory")
#define CP_WAIT1()  asm volatile("cp.async.wait_group 1;" ::: "memory")
#define CP_WAIT0()  asm volatile("cp.async.wait_group 0;" ::: "memory")

__global__ void __launch_bounds__(256) gemm_mma() {
    extern __shared__ __nv_bfloat16 sm[];

    int nc   = blockIdx.x;      // 0..3 : output col block of 128
    int rb   = blockIdx.y;      // row block of 128
    int side = blockIdx.z;
    int tid = threadIdx.x, wid = tid >> 5, lane = tid & 31;
    int wm = wid & 3, wn = wid >> 2;

    const __nv_bfloat16* Agh = g_Xh + (size_t)side * NN * 256 + (size_t)rb * 128 * 256;
    const __nv_bfloat16* Agl = g_Xl + (size_t)side * NN * 256 + (size_t)rb * 128 * 256;
    const __nv_bfloat16* Bgh = g_Mh + side * 512 * 256 + nc * 128 * 256;
    const __nv_bfloat16* Bgl = g_Ml + side * 512 * 256 + nc * 128 * 256;

    float c[2][8][4];
#pragma unroll
    for (int mt = 0; mt < 2; mt++)
#pragma unroll
        for (int nt = 0; nt < 8; nt++)
#pragma unroll
            for (int q = 0; q < 4; q++) c[mt][nt][q] = 0.f;

    uint32_t sb = smem_to_u32(sm);

    // issue async loads for chunk kc into stage st (4 x 16B per thread per matrix)
    auto issue_chunk = [&](int kc, int st) {
        uint32_t s0 = sb + (uint32_t)st * STAGE_BYTES;
#pragma unroll
        for (int i = 0; i < 4; i++) {
            int idx = tid + i * 256;                 // [0,1024)
            int row = idx >> 3, cg = idx & 7;
            size_t goff = (size_t)row * 256 + kc * 64 + cg * 8;
            uint32_t soff = (uint32_t)(row * SROW + cg * 8) * 2;
            CP_ASYNC16(s0 + 0 * MAT_BYTES + soff, Agh + goff);
            CP_ASYNC16(s0 + 1 * MAT_BYTES + soff, Agl + goff);
            CP_ASYNC16(s0 + 2 * MAT_BYTES + soff, Bgh + goff);
            CP_ASYNC16(s0 + 3 * MAT_BYTES + soff, Bgl + goff);
        }
        CP_COMMIT();
    };

    // prologue: chunks 0 and 1 in flight
    issue_chunk(0, 0);
    issue_chunk(1, 1);

    for (int kc = 0; kc < 4; kc++) {
        int st = kc & 1;
        if (kc < 3) { CP_WAIT1(); } else { CP_WAIT0(); }
        __syncthreads();                         // stage st data visible block-wide

        uint32_t base = sb + (uint32_t)st * STAGE_BYTES;
        uint32_t baseA = base;                   // Ah
        uint32_t baseB = base + 2 * MAT_BYTES;   // Bh

#pragma unroll
        for (int ks = 0; ks < 4; ks++) {
            int k0 = ks * 16;
            uint32_t ah[2][4], al[2][4], bh[8][2], bl[8][2];
#pragma unroll
            for (int mt = 0; mt < 2; mt++) {
                int r = wm * 32 + mt * 16 + (lane & 15);
                uint32_t addr = baseA + (uint32_t)(r * SROW + k0 + (lane >> 4) * 8) * 2;
                LDSM_X4(ah[mt], addr);
                LDSM_X4(al[mt], addr + MAT_BYTES);
            }
#pragma unroll
            for (int nt = 0; nt < 8; nt++) {
                int n = wn * 64 + nt * 8 + (lane & 7);
                uint32_t addr = baseB + (uint32_t)(n * SROW + k0 + ((lane >> 3) & 1) * 8) * 2;
                LDSM_X2(bh[nt], addr);
                LDSM_X2(bl[nt], addr + MAT_BYTES);
            }
#pragma unroll
            for (int mt = 0; mt < 2; mt++)
#pragma unroll
                for (int nt = 0; nt < 8; nt++) {
                    MMA16816(c[mt][nt], ah[mt], bh[nt]);
                    MMA16816(c[mt][nt], al[mt], bh[nt]);
                    MMA16816(c[mt][nt], ah[mt], bl[nt]);
                }
        }

        __syncthreads();                         // all threads done reading stage st
        if (kc < 2) issue_chunk(kc + 2, st);     // refill freed stage
    }

    // epilogue: add bias, store fp32
    const float* bias = g_bM + side * 512;
    float* out = side ? g_QKb : g_QKa;
    int col0 = nc * 128 + wn * 64;
#pragma unroll
    for (int mt = 0; mt < 2; mt++) {
        int r0 = rb * 128 + wm * 32 + mt * 16 + (lane >> 2);
#pragma unroll
        for (int nt = 0; nt < 8; nt++) {
            int cb = col0 + nt * 8 + (lane & 3) * 2;
            float2 bv = *reinterpret_cast<const float2*>(bias + cb);
            float2 v0, v1;
            v0.x = c[mt][nt][0] + bv.x;  v0.y = c[mt][nt][1] + bv.y;
            v1.x = c[mt][nt][2] + bv.x;  v1.y = c[mt][nt][3] + bv.y;
            *reinterpret_cast<float2*>(out + (size_t)r0 * 512 + cb) = v0;
            *reinterpret_cast<float2*>(out + (size_t)(r0 + 8) * 512 + cb) = v1;
        }
    }
}

// ---------------- edge kernel: attention weights + S0/S1 scatter -------------
__global__ void __launch_bounds__(256) edge_kernel(const int* __restrict__ ei,
                                                   const float* __restrict__ ea,
                                                   int E, int pass) {
    int gid = blockIdx.x * blockDim.x + threadIdx.x;
    int e = gid >> 5;
    int lane = gid & 31;
    if (e >= E) return;

    const float* Q;
    const float* K;
    float* S;
    if (pass == 0) { Q = g_QKb;       K = g_QKa;       S = g_Sb; }
    else           { Q = g_QKa + 256; K = g_QKb + 256; S = g_Sa; }

    int src = ei[e];
    int dst = ei[E + e];
    float eav = ea[e];

    int pair = lane & 15;
    int h = pair >> 2;
    int qi = pair & 3;
    int half = lane >> 4;
    int ki0 = half * 2;

    const float4* qp  = reinterpret_cast<const float4*>(Q + (size_t)dst * 512 + qi * 64 + h * 16);
    const float4* kp0 = reinterpret_cast<const float4*>(K + (size_t)src * 512 + ki0 * 64 + h * 16);
    const float4* kp1 = reinterpret_cast<const float4*>(K + (size_t)src * 512 + (ki0 + 1) * 64 + h * 16);

    float s0 = 0.f, s1 = 0.f;
#pragma unroll
    for (int t = 0; t < 4; t++) {
        float4 q4 = qp[t];
        float4 k4 = kp0[t];
        float4 k5 = kp1[t];
        s0 += q4.x * k4.x + q4.y * k4.y + q4.z * k4.z + q4.w * k4.w;
        s1 += q4.x * k5.x + q4.y * k5.y + q4.z * k5.z + q4.w * k5.w;
    }
    s0 *= SCALE_ATT;
    s1 *= SCALE_ATT;

    float o0 = __shfl_xor_sync(0xffffffffu, s0, 16);
    float o1 = __shfl_xor_sync(0xffffffffu, s1, 16);
    float mx = fmaxf(fmaxf(s0, s1), fmaxf(o0, o1));
    float e0  = __expf(s0 - mx), e1  = __expf(s1 - mx);
    float eo0 = __expf(o0 - mx), eo1 = __expf(o1 - mx);
    float inv = 1.f / (e0 + e1 + eo0 + eo1);
    float a0 = e0 * inv, a1 = e1 * inv;

    float* Sp = S + (size_t)dst * 128 + h * 16 + qi * 4;
    atomicAdd(Sp + ki0,          a0);
    atomicAdd(Sp + ki0 + 1,      a1);
    atomicAdd(Sp + 64 + ki0,     eav * a0);
    atomicAdd(Sp + 64 + ki0 + 1, eav * a1);
}

// ---------------- warp all-reduce -------------------------------------------
__device__ __forceinline__ float warp_sum(float x) {
    x += __shfl_xor_sync(0xffffffffu, x, 16);
    x += __shfl_xor_sync(0xffffffffu, x, 8);
    x += __shfl_xor_sync(0xffffffffu, x, 4);
    x += __shfl_xor_sync(0xffffffffu, x, 2);
    x += __shfl_xor_sync(0xffffffffu, x, 1);
    return x;
}

// ---------------- post kernel: y = LN(S @ M2^T + deg*vb + bo) ----------------
__global__ void __launch_bounds__(256) post_kernel(const float* __restrict__ bo,
                                                   const float* __restrict__ lng,
                                                   const float* __restrict__ lnb,
                                                   float* __restrict__ outbase,
                                                   int side, int Nn) {
    const float* S  = side ? g_Sb  : g_Sa;
    const float* M2 = side ? g_M2b : g_M2a;
    const float* vb = side ? g_vbb : g_vba;
    float* out = outbase + (size_t)side * Nn * 256;

    __shared__ float Ss[32 * 128];
    __shared__ float Ms[16][256];

    int tid = threadIdx.x;
    int n0 = blockIdx.x * 32;

    {
        const float4* Sg = reinterpret_cast<const float4*>(S + (size_t)n0 * 128);
        float4* Sd = reinterpret_cast<float4*>(Ss);
#pragma unroll
        for (int i = 0; i < 4; i++) Sd[tid + i * 256] = Sg[tid + i * 256];
    }

    int trow = tid >> 5, tcol = tid & 31;
    float acc[4][8];
#pragma unroll
    for (int i = 0; i < 4; i++)
#pragma unroll
        for (int j = 0; j < 8; j++) acc[i][j] = 0.f;

    for (int kb = 0; kb < 8; kb++) {
        __syncthreads();
        {
            const float4* m4 = reinterpret_cast<const float4*>(M2 + (size_t)tid * 128 + kb * 16);
            float4 v0 = m4[0], v1 = m4[1], v2 = m4[2], v3 = m4[3];
            Ms[0][tid] = v0.x;  Ms[1][tid] = v0.y;  Ms[2][tid] = v0.z;  Ms[3][tid] = v0.w;
            Ms[4][tid] = v1.x;  Ms[5][tid] = v1.y;  Ms[6][tid] = v1.z;  Ms[7][tid] = v1.w;
            Ms[8][tid] = v2.x;  Ms[9][tid] = v2.y;  Ms[10][tid] = v2.z; Ms[11][tid] = v2.w;
            Ms[12][tid] = v3.x; Ms[13][tid] = v3.y; Ms[14][tid] = v3.z; Ms[15][tid] = v3.w;
        }
        __syncthreads();
#pragma unroll
        for (int kk = 0; kk < 16; kk++) {
            float a0 = Ss[(trow * 4 + 0) * 128 + kb * 16 + kk];
            float a1 = Ss[(trow * 4 + 1) * 128 + kb * 16 + kk];
            float a2 = Ss[(trow * 4 + 2) * 128 + kb * 16 + kk];
            float a3 = Ss[(trow * 4 + 3) * 128 + kb * 16 + kk];
            float4 b0 = *reinterpret_cast<const float4*>(&Ms[kk][tcol * 8]);
            float4 b1 = *reinterpret_cast<const float4*>(&Ms[kk][tcol * 8 + 4]);
            float b[8] = {b0.x, b0.y, b0.z, b0.w, b1.x, b1.y, b1.z, b1.w};
#pragma unroll
            for (int j = 0; j < 8; j++) {
                acc[0][j] += a0 * b[j];
                acc[1][j] += a1 * b[j];
                acc[2][j] += a2 * b[j];
                acc[3][j] += a3 * b[j];
            }
        }
    }

    float4 vb0 = *reinterpret_cast<const float4*>(&vb[tcol * 8]);
    float4 vb1 = *reinterpret_cast<const float4*>(&vb[tcol * 8 + 4]);
    float4 bo0 = *reinterpret_cast<const float4*>(&bo[tcol * 8]);
    float4 bo1 = *reinterpret_cast<const float4*>(&bo[tcol * 8 + 4]);
    float4 g0  = *reinterpret_cast<const float4*>(&lng[tcol * 8]);
    float4 g1  = *reinterpret_cast<const float4*>(&lng[tcol * 8 + 4]);
    float4 lb0 = *reinterpret_cast<const float4*>(&lnb[tcol * 8]);
    float4 lb1 = *reinterpret_cast<const float4*>(&lnb[tcol * 8 + 4]);
    float vbv[8] = {vb0.x, vb0.y, vb0.z, vb0.w, vb1.x, vb1.y, vb1.z, vb1.w};
    float bov[8] = {bo0.x, bo0.y, bo0.z, bo0.w, bo1.x, bo1.y, bo1.z, bo1.w};
    float gv[8]  = {g0.x, g0.y, g0.z, g0.w, g1.x, g1.y, g1.z, g1.w};
    float bvv[8] = {lb0.x, lb0.y, lb0.z, lb0.w, lb1.x, lb1.y, lb1.z, lb1.w};

#pragma unroll
    for (int i = 0; i < 4; i++) {
        int base = (trow * 4 + i) * 128;
        float deg = Ss[base] + Ss[base + 1] + Ss[base + 2] + Ss[base + 3];
        float v[8];
        float psum = 0.f;
#pragma unroll
        for (int j = 0; j < 8; j++) {
            v[j] = acc[i][j] + deg * vbv[j] + bov[j];
            psum += v[j];
        }
        float mean = warp_sum(psum) * (1.f / 256.f);
        float psq = 0.f;
#pragma unroll
        for (int j = 0; j < 8; j++) {
            float d = v[j] - mean;
            psq += d * d;
        }
        float var = warp_sum(psq) * (1.f / 256.f);
        float rs = rsqrtf(var + EPS_LN);

        int row = n0 + trow * 4 + i;
        float4 o0, o1;
        o0.x = (v[0] - mean) * rs * gv[0] + bvv[0];
        o0.y = (v[1] - mean) * rs * gv[1] + bvv[1];
        o0.z = (v[2] - mean) * rs * gv[2] + bvv[2];
        o0.w = (v[3] - mean) * rs * gv[3] + bvv[3];
        o1.x = (v[4] - mean) * rs * gv[4] + bvv[4];
        o1.y = (v[5] - mean) * rs * gv[5] + bvv[5];
        o1.z = (v[6] - mean) * rs * gv[6] + bvv[6];
        o1.w = (v[7] - mean) * rs * gv[7] + bvv[7];
        float* op = out + (size_t)row * 256 + tcol * 8;
        *reinterpret_cast<float4*>(op) = o0;
        *reinterpret_cast<float4*>(op + 4) = o1;
    }
}

// ---------------- launch ------------------------------------------------------
extern "C" void kernel_launch(void* const* d_in, const int* in_sizes, int n_in,
                              void* d_out, int out_size) {
    const float* x_a   = (const float*)d_in[0];
    const float* x_b   = (const float*)d_in[1];
    const int*   ei1   = (const int*)d_in[2];
    const float* ea1   = (const float*)d_in[3];
    const int*   ei2   = (const int*)d_in[4];
    const float* ea2   = (const float*)d_in[5];
    const float* Wn_a  = (const float*)d_in[6];
    const float* bn_a  = (const float*)d_in[7];
    const float* Wn_b  = (const float*)d_in[8];
    const float* bn_b  = (const float*)d_in[9];
    const float* We1   = (const float*)d_in[10];
    const float* be1   = (const float*)d_in[11];
    const float* Win1  = (const float*)d_in[12];
    const float* bin1  = (const float*)d_in[13];
    const float* Wout1 = (const float*)d_in[14];
    const float* bout1 = (const float*)d_in[15];
    const float* We2   = (const float*)d_in[16];
    const float* be2   = (const float*)d_in[17];
    const float* Win2  = (const float*)d_in[18];
    const float* bin2  = (const float*)d_in[19];
    const float* Wout2 = (const float*)d_in[20];
    const float* bout2 = (const float*)d_in[21];
    const float* Wo_a  = (const float*)d_in[22];
    const float* bo_a  = (const float*)d_in[23];
    const float* Wo_b  = (const float*)d_in[24];
    const float* bo_b  = (const float*)d_in[25];
    const float* ln_g  = (const float*)d_in[26];
    const float* ln_b  = (const float*)d_in[27];

    const int N = in_sizes[0] / 256;
    const int E = in_sizes[2] / 2;

    cudaFuncSetAttribute(gemm_mma, cudaFuncAttributeMaxDynamicSharedMemorySize, GEMM_SMEM);

    clear_S<<<2048, 256>>>();

    // bf16 hi/lo conversion of X
    {
        dim3 cg((NN * 256 / 4 + 255) / 256, 2);
        convert_X<<<cg, 256>>>(x_a, x_b);
    }

    // side a (from x_a): rows 0-255 = K1 map (Wk1 = Win1+64*64), rows 256-511 = Q2 map (Wq2 = Win2)
    combine_qk<<<512, 256>>>(0, Wn_a, bn_a, Win1 + 64 * 64, bin1 + 64, Win2, bin2);
    // side b (from x_b): rows 0-255 = Q1 map (Wq1 = Win1), rows 256-511 = K2 map (Wk2 = Win2+64*64)
    combine_qk<<<512, 256>>>(1, Wn_b, bn_b, Win1, bin1, Win2 + 64 * 64, bin2 + 64);
    compute_uw<<<1, 256>>>(0, Win1, bin1, We1, be1);
    compute_uw<<<1, 256>>>(1, Win2, bin2, We2, be2);
    compute_T<<<256, 256>>>(0, Wo_a, Wout2);
    compute_T<<<256, 256>>>(1, Wo_b, Wout1);
    compute_M2<<<128, 256>>>(0, Wo_a, bout2);
    compute_M2<<<128, 256>>>(1, Wo_b, bout1);

    // tensor-core QK projections (both sides): grid (nc, rowblocks, side)
    {
        dim3 gg(4, N / 128, 2);
        gemm_mma<<<gg, 256, GEMM_SMEM>>>();
    }

    // edge passes (attention + scatter)
    int eblocks = (E * 32 + 255) / 256;
    edge_kernel<<<eblocks, 256>>>(ei1, ea1, E, 0);   // -> g_Sb (out_b)
    edge_kernel<<<eblocks, 256>>>(ei2, ea2, E, 1);   // -> g_Sa (out_a)

    // fused node-level postprocess + LayerNorm
    post_kernel<<<N / 32, 256>>>(bo_a, ln_g, ln_b, (float*)d_out, 0, N);  // y_a
    post_kernel<<<N / 32, 256>>>(bo_b, ln_g, ln_b, (float*)d_out, 1, N);  // y_b
}

// round 14
// speedup vs baseline: 1.0828x; 1.0828x over previous
#include <cuda_runtime.h>
#include <cuda_bf16.h>
#include <cstdint>

// Problem constants (fixed by the dataset)
#define NN 65536
#define EE 131072
#define EPS_LN 1e-5f
#define SCALE_ATT 0.25f   // HD^-0.5, HD=16

// ---------------- scratch (device globals; no allocation allowed) ------------
__device__ __nv_bfloat16 g_QKa[(size_t)NN * 512];   // [K1 | Q2] from x_a (bf16)
__device__ __nv_bfloat16 g_QKb[(size_t)NN * 512];   // [Q1 | K2] from x_b (bf16)
__device__ float g_Sa[(size_t)NN * 128];    // scatter target for pass2 (out_a)
__device__ float g_Sb[(size_t)NN * 128];    // scatter target for pass1 (out_b)
__device__ __nv_bfloat16 g_Xh[(size_t)2 * NN * 256];  // bf16 hi of x_a|x_b
__device__ __nv_bfloat16 g_Xl[(size_t)2 * NN * 256];  // bf16 residual
__device__ __nv_bfloat16 g_Mh[2 * 512 * 256];         // combined QK weights hi
__device__ __nv_bfloat16 g_Ml[2 * 512 * 256];         // combined QK weights lo
__device__ float g_bM[2 * 512];
__device__ float g_u1[4 * 64], g_w1[4 * 64];
__device__ float g_u2[4 * 64], g_w2[4 * 64];
__device__ float g_Ta[256 * 256], g_Tb[256 * 256];  // Wo @ BD(Wout)
__device__ float g_M2a[256 * 128], g_M2b[256 * 128];
__device__ float g_vba[256], g_vbb[256];

__device__ __forceinline__ uint32_t smem_to_u32(const void* p) {
    uint32_t a;
    asm("{ .reg .u64 t; cvta.to.shared.u64 t, %1; cvt.u32.u64 %0, t; }" : "=r"(a) : "l"(p));
    return a;
}

// ---------------- zero the scatter accumulators ------------------------------
__global__ void clear_S() {
    int i = blockIdx.x * blockDim.x + threadIdx.x;
    int stride = gridDim.x * blockDim.x;
    float4 z = make_float4(0.f, 0.f, 0.f, 0.f);
    float4* A = reinterpret_cast<float4*>(g_Sa);
    float4* B = reinterpret_cast<float4*>(g_Sb);
    const int total = NN * 128 / 4;
    for (int t = i; t < total; t += stride) { A[t] = z; B[t] = z; }
}

// ---------------- convert X to bf16 hi/lo ------------------------------------
__global__ void convert_X(const float* __restrict__ xa, const float* __restrict__ xb) {
    int side = blockIdx.y;
    const float* X = side ? xb : xa;
    size_t i = (size_t)blockIdx.x * blockDim.x + threadIdx.x;  // group of 4 floats
    const size_t total = (size_t)NN * 256 / 4;
    if (i >= total) return;
    float4 v = reinterpret_cast<const float4*>(X)[i];
    __nv_bfloat16 h0 = __float2bfloat16(v.x), h1 = __float2bfloat16(v.y);
    __nv_bfloat16 h2 = __float2bfloat16(v.z), h3 = __float2bfloat16(v.w);
    __nv_bfloat16 l0 = __float2bfloat16(v.x - __bfloat162float(h0));
    __nv_bfloat16 l1 = __float2bfloat16(v.y - __bfloat162float(h1));
    __nv_bfloat16 l2 = __float2bfloat16(v.z - __bfloat162float(h2));
    __nv_bfloat16 l3 = __float2bfloat16(v.w - __bfloat162float(h3));
    __nv_bfloat162* H = reinterpret_cast<__nv_bfloat162*>(g_Xh + (size_t)side * NN * 256);
    __nv_bfloat162* L = reinterpret_cast<__nv_bfloat162*>(g_Xl + (size_t)side * NN * 256);
    H[i * 2]     = __nv_bfloat162(h0, h1);
    H[i * 2 + 1] = __nv_bfloat162(h2, h3);
    L[i * 2]     = __nv_bfloat162(l0, l1);
    L[i * 2 + 1] = __nv_bfloat162(l2, l3);
}

// ---------------- combined QK weight precompute (bf16 hi/lo output) ----------
__global__ void combine_qk(int side,
                           const float* __restrict__ Wn, const float* __restrict__ bn,
                           const float* __restrict__ Wf, const float* __restrict__ bf,
                           const float* __restrict__ Ws, const float* __restrict__ bs) {
    __nv_bfloat16* Mh = g_Mh + side * 512 * 256;
    __nv_bfloat16* Ml = g_Ml + side * 512 * 256;
    float* bias = g_bM + side * 512;
    int idx = blockIdx.x * blockDim.x + threadIdx.x;  // 512*256 threads
    int jout = idx >> 8;        // 0..511
    int c    = idx & 255;
    int hsel = jout >> 8;
    int jo   = jout & 255;
    int g = jo >> 6, j = jo & 63;
    const float* Wsub = hsel ? Ws : Wf;
    float acc = 0.f;
#pragma unroll 8
    for (int d = 0; d < 64; d++)
        acc += Wsub[j * 64 + d] * Wn[(g * 64 + d) * 256 + c];
    __nv_bfloat16 h = __float2bfloat16(acc);
    Mh[jout * 256 + c] = h;
    Ml[jout * 256 + c] = __float2bfloat16(acc - __bfloat162float(h));
    if (c == 0) {
        const float* bsub = hsel ? bs : bf;
        float bacc = bsub[j];
#pragma unroll 8
        for (int d = 0; d < 64; d++) bacc += Wsub[j * 64 + d] * bn[g * 64 + d];
        bias[jout] = bacc;
    }
}

// ---------------- u/w precompute ---------------------------------------------
__global__ void compute_uw(int pass, const float* __restrict__ Win,
                           const float* __restrict__ bin,
                           const float* __restrict__ We, const float* __restrict__ be) {
    float* u = pass ? g_u2 : g_u1;
    float* w = pass ? g_w2 : g_w1;
    int t = threadIdx.x;
    int ki = t >> 6, j = t & 63;
    const float* Wv = Win + 128 * 64;
    float su = 0.f, sw = 0.f;
#pragma unroll 8
    for (int d = 0; d < 64; d++) {
        float wv = Wv[j * 64 + d];
        su += wv * We[ki * 64 + d];
        sw += wv * be[ki * 64 + d];
    }
    u[t] = su;
    w[t] = sw + bin[128 + j];
}

// ---------------- T = Wo @ BD(Wout) ------------------------------------------
__global__ void compute_T(int side, const float* __restrict__ Wo,
                          const float* __restrict__ Wout) {
    float* T = side ? g_Tb : g_Ta;
    int idx = blockIdx.x * 256 + threadIdx.x;
    int r = idx >> 8, qo = idx & 255;
    int qi = qo >> 6, j = qo & 63;
    float acc = 0.f;
#pragma unroll 8
    for (int jj = 0; jj < 64; jj++)
        acc += Wo[r * 256 + qi * 64 + jj] * Wout[jj * 64 + j];
    T[idx] = acc;
}

// ---------------- M2 = T @ G(u,w) --------------------------------------------
__global__ void compute_M2(int side, const float* __restrict__ Wo,
                           const float* __restrict__ bout) {
    const float* T = side ? g_Tb : g_Ta;
    const float* u = side ? g_u1 : g_u2;
    const float* w = side ? g_w1 : g_w2;
    float* M2 = side ? g_M2b : g_M2a;
    float* vb = side ? g_vbb : g_vba;
    int idx = blockIdx.x * 256 + threadIdx.x;
    int r = idx >> 7, s = idx & 127;
    int z = s >> 6;
    int rest = s & 63;
    int h = rest >> 4, qr = (rest >> 2) & 3, ki = rest & 3;
    const float* coef = z ? u : w;
    float acc = 0.f;
#pragma unroll
    for (int hd = 0; hd < 16; hd++)
        acc += T[r * 256 + qr * 64 + h * 16 + hd] * coef[ki * 64 + h * 16 + hd];
    M2[r * 128 + s] = acc;
    if (s == 0) {
        float b = 0.f;
        for (int qi2 = 0; qi2 < 4; qi2++)
#pragma unroll 8
            for (int jj = 0; jj < 64; jj++)
                b += Wo[r * 256 + qi2 * 64 + jj] * bout[jj];
        vb[r] = b;
    }
}

// ---------------- mma.sync QK GEMM -------------------------------------------
// out[N,512](bf16) = X[N,256] @ M^T + bias, split-bf16 3-term, fp32 accum.
// Block: 256 threads (8 warps, 4m x 2n), tile 128M x 128N, K in 4 chunks of 64.
// grid: (4 nc, N/128 rows, 2 sides) — nc fastest for L2 reuse of A.
#define SROW 72   // padded bf16 stride in smem (144B rows -> conflict-free)
#define GEMM_SMEM (4 * 128 * SROW * 2)   // 73728 B

#define LDSM_X4(r, addr) \
    asm volatile("ldmatrix.sync.aligned.m8n8.x4.shared.b16 {%0,%1,%2,%3}, [%4];" \
        : "=r"((r)[0]), "=r"((r)[1]), "=r"((r)[2]), "=r"((r)[3]) : "r"(addr))
#define LDSM_X2(r, addr) \
    asm volatile("ldmatrix.sync.aligned.m8n8.x2.shared.b16 {%0,%1}, [%2];" \
        : "=r"((r)[0]), "=r"((r)[1]) : "r"(addr))
#define MMA16816(c, a, b) \
    asm volatile("mma.sync.aligned.m16n8k16.row.col.f32.bf16.bf16.f32 " \
        "{%0,%1,%2,%3}, {%4,%5,%6,%7}, {%8,%9}, {%0,%1,%2,%3};" \
        : "+f"((c)[0]), "+f"((c)[1]), "+f"((c)[2]), "+f"((c)[3]) \
        : "r"((a)[0]), "r"((a)[1]), "r"((a)[2]), "r"((a)[3]), "r"((b)[0]), "r"((b)[1]))

__global__ void __launch_bounds__(256) gemm_mma() {
    extern __shared__ __nv_bfloat16 sm[];
    __nv_bfloat16* sAh = sm;                 // 128*72
    __nv_bfloat16* sAl = sm + 128 * SROW;
    __nv_bfloat16* sBh = sm + 2 * 128 * SROW;
    __nv_bfloat16* sBl = sm + 3 * 128 * SROW;

    int nc   = blockIdx.x;      // 0..3 : output col block of 128
    int rb   = blockIdx.y;      // row block of 128
    int side = blockIdx.z;
    int tid = threadIdx.x, wid = tid >> 5, lane = tid & 31;
    int wm = wid & 3, wn = wid >> 2;

    const __nv_bfloat16* Agh = g_Xh + (size_t)side * NN * 256 + (size_t)rb * 128 * 256;
    const __nv_bfloat16* Agl = g_Xl + (size_t)side * NN * 256 + (size_t)rb * 128 * 256;
    const __nv_bfloat16* Bgh = g_Mh + side * 512 * 256 + nc * 128 * 256;
    const __nv_bfloat16* Bgl = g_Ml + side * 512 * 256 + nc * 128 * 256;

    float c[2][8][4];
#pragma unroll
    for (int mt = 0; mt < 2; mt++)
#pragma unroll
        for (int nt = 0; nt < 8; nt++)
#pragma unroll
            for (int q = 0; q < 4; q++) c[mt][nt][q] = 0.f;

    uint32_t sb = smem_to_u32(sm);
    const uint32_t offAl = 128 * SROW * 2;          // bytes
    const uint32_t offBh = 2 * 128 * SROW * 2;
    const uint32_t offBl = 3 * 128 * SROW * 2;

    for (int kc = 0; kc < 4; kc++) {
        __syncthreads();
        // load chunk: A/B hi+lo, 128 rows x 64 cols each
#pragma unroll
        for (int i = 0; i < 4; i++) {
            int idx = tid + i * 256;                // [0,1024)
            int row = idx >> 3, cg = idx & 7;
            size_t goff = (size_t)row * 256 + kc * 64 + cg * 8;
            int soff = row * SROW + cg * 8;
            *reinterpret_cast<uint4*>(sAh + soff) = *reinterpret_cast<const uint4*>(Agh + goff);
            *reinterpret_cast<uint4*>(sAl + soff) = *reinterpret_cast<const uint4*>(Agl + goff);
            *reinterpret_cast<uint4*>(sBh + soff) = *reinterpret_cast<const uint4*>(Bgh + goff);
            *reinterpret_cast<uint4*>(sBl + soff) = *reinterpret_cast<const uint4*>(Bgl + goff);
        }
        __syncthreads();

#pragma unroll
        for (int ks = 0; ks < 4; ks++) {
            int k0 = ks * 16;
            uint32_t ah[2][4], al[2][4], bh[8][2], bl[8][2];
#pragma unroll
            for (int mt = 0; mt < 2; mt++) {
                int r = wm * 32 + mt * 16 + (lane & 15);
                uint32_t addr = sb + (uint32_t)(r * SROW + k0 + (lane >> 4) * 8) * 2;
                LDSM_X4(ah[mt], addr);
                LDSM_X4(al[mt], addr + offAl);
            }
#pragma unroll
            for (int nt = 0; nt < 8; nt++) {
                int n = wn * 64 + nt * 8 + (lane & 7);
                uint32_t addr = sb + offBh + (uint32_t)(n * SROW + k0 + ((lane >> 3) & 1) * 8) * 2;
                LDSM_X2(bh[nt], addr);
                LDSM_X2(bl[nt], addr + (offBl - offBh));
            }
#pragma unroll
            for (int mt = 0; mt < 2; mt++)
#pragma unroll
                for (int nt = 0; nt < 8; nt++) {
                    MMA16816(c[mt][nt], ah[mt], bh[nt]);
                    MMA16816(c[mt][nt], al[mt], bh[nt]);
                    MMA16816(c[mt][nt], ah[mt], bl[nt]);
                }
        }
    }

    // epilogue: add bias, store bf16
    const float* bias = g_bM + side * 512;
    __nv_bfloat16* out = side ? g_QKb : g_QKa;
    int col0 = nc * 128 + wn * 64;
#pragma unroll
    for (int mt = 0; mt < 2; mt++) {
        int r0 = rb * 128 + wm * 32 + mt * 16 + (lane >> 2);
#pragma unroll
        for (int nt = 0; nt < 8; nt++) {
            int cb = col0 + nt * 8 + (lane & 3) * 2;
            float2 bv = *reinterpret_cast<const float2*>(bias + cb);
            __nv_bfloat162 p0 = __floats2bfloat162_rn(c[mt][nt][0] + bv.x, c[mt][nt][1] + bv.y);
            __nv_bfloat162 p1 = __floats2bfloat162_rn(c[mt][nt][2] + bv.x, c[mt][nt][3] + bv.y);
            *reinterpret_cast<__nv_bfloat162*>(out + (size_t)r0 * 512 + cb) = p0;
            *reinterpret_cast<__nv_bfloat162*>(out + (size_t)(r0 + 8) * 512 + cb) = p1;
        }
    }
}

// ---------------- edge kernel: attention weights + S0/S1 scatter -------------
// one warp per edge; lane layout: pair = lane&15 -> (h, qi); half = lane>>4 -> ki pair
__global__ void __launch_bounds__(256) edge_kernel(const int* __restrict__ ei,
                                                   const float* __restrict__ ea,
                                                   int E, int pass) {
    int gid = blockIdx.x * blockDim.x + threadIdx.x;
    int e = gid >> 5;
    int lane = gid & 31;
    if (e >= E) return;

    const __nv_bfloat16* Q;
    const __nv_bfloat16* K;
    float* S;
    if (pass == 0) { Q = g_QKb;       K = g_QKa;       S = g_Sb; }
    else           { Q = g_QKa + 256; K = g_QKb + 256; S = g_Sa; }

    int src = ei[e];
    int dst = ei[E + e];
    float eav = ea[e];

    int pair = lane & 15;
    int h = pair >> 2;
    int qi = pair & 3;
    int half = lane >> 4;
    int ki0 = half * 2;

    // 16 bf16 (32B) per operand, loaded as 2 x uint4
    const uint4* qp  = reinterpret_cast<const uint4*>(Q + (size_t)dst * 512 + qi * 64 + h * 16);
    const uint4* kp0 = reinterpret_cast<const uint4*>(K + (size_t)src * 512 + ki0 * 64 + h * 16);
    const uint4* kp1 = reinterpret_cast<const uint4*>(K + (size_t)src * 512 + (ki0 + 1) * 64 + h * 16);

    uint4 qv[2]  = {qp[0], qp[1]};
    uint4 k0v[2] = {kp0[0], kp0[1]};
    uint4 k1v[2] = {kp1[0], kp1[1]};
    const __nv_bfloat162* q2 = reinterpret_cast<const __nv_bfloat162*>(qv);
    const __nv_bfloat162* a2 = reinterpret_cast<const __nv_bfloat162*>(k0v);
    const __nv_bfloat162* b2 = reinterpret_cast<const __nv_bfloat162*>(k1v);

    float s0 = 0.f, s1 = 0.f;
#pragma unroll
    for (int t = 0; t < 8; t++) {
        float2 qf = __bfloat1622float2(q2[t]);
        float2 ka = __bfloat1622float2(a2[t]);
        float2 kb = __bfloat1622float2(b2[t]);
        s0 += qf.x * ka.x + qf.y * ka.y;
        s1 += qf.x * kb.x + qf.y * kb.y;
    }
    s0 *= SCALE_ATT;
    s1 *= SCALE_ATT;

    float o0 = __shfl_xor_sync(0xffffffffu, s0, 16);
    float o1 = __shfl_xor_sync(0xffffffffu, s1, 16);
    float mx = fmaxf(fmaxf(s0, s1), fmaxf(o0, o1));
    float e0  = __expf(s0 - mx), e1  = __expf(s1 - mx);
    float eo0 = __expf(o0 - mx), eo1 = __expf(o1 - mx);
    float inv = 1.f / (e0 + e1 + eo0 + eo1);
    float a0 = e0 * inv, a1 = e1 * inv;

    float* Sp = S + (size_t)dst * 128 + h * 16 + qi * 4;
    atomicAdd(Sp + ki0,          a0);
    atomicAdd(Sp + ki0 + 1,      a1);
    atomicAdd(Sp + 64 + ki0,     eav * a0);
    atomicAdd(Sp + 64 + ki0 + 1, eav * a1);
}

// ---------------- warp all-reduce -------------------------------------------
__device__ __forceinline__ float warp_sum(float x) {
    x += __shfl_xor_sync(0xffffffffu, x, 16);
    x += __shfl_xor_sync(0xffffffffu, x, 8);
    x += __shfl_xor_sync(0xffffffffu, x, 4);
    x += __shfl_xor_sync(0xffffffffu, x, 2);
    x += __shfl_xor_sync(0xffffffffu, x, 1);
    return x;
}

// ---------------- post kernel: y = LN(S @ M2^T + deg*vb + bo) ----------------
__global__ void __launch_bounds__(256) post_kernel(const float* __restrict__ bo,
                                                   const float* __restrict__ lng,
                                                   const float* __restrict__ lnb,
                                                   float* __restrict__ outbase,
                                                   int side, int Nn) {
    const float* S  = side ? g_Sb  : g_Sa;
    const float* M2 = side ? g_M2b : g_M2a;
    const float* vb = side ? g_vbb : g_vba;
    float* out = outbase + (size_t)side * Nn * 256;

    __shared__ float Ss[32 * 128];
    __shared__ float Ms[16][256];

    int tid = threadIdx.x;
    int n0 = blockIdx.x * 32;

    {
        const float4* Sg = reinterpret_cast<const float4*>(S + (size_t)n0 * 128);
        float4* Sd = reinterpret_cast<float4*>(Ss);
#pragma unroll
        for (int i = 0; i < 4; i++) Sd[tid + i * 256] = Sg[tid + i * 256];
    }

    int trow = tid >> 5, tcol = tid & 31;
    float acc[4][8];
#pragma unroll
    for (int i = 0; i < 4; i++)
#pragma unroll
        for (int j = 0; j < 8; j++) acc[i][j] = 0.f;

    for (int kb = 0; kb < 8; kb++) {
        __syncthreads();
        {
            const float4* m4 = reinterpret_cast<const float4*>(M2 + (size_t)tid * 128 + kb * 16);
            float4 v0 = m4[0], v1 = m4[1], v2 = m4[2], v3 = m4[3];
            Ms[0][tid] = v0.x;  Ms[1][tid] = v0.y;  Ms[2][tid] = v0.z;  Ms[3][tid] = v0.w;
            Ms[4][tid] = v1.x;  Ms[5][tid] = v1.y;  Ms[6][tid] = v1.z;  Ms[7][tid] = v1.w;
            Ms[8][tid] = v2.x;  Ms[9][tid] = v2.y;  Ms[10][tid] = v2.z; Ms[11][tid] = v2.w;
            Ms[12][tid] = v3.x; Ms[13][tid] = v3.y; Ms[14][tid] = v3.z; Ms[15][tid] = v3.w;
        }
        __syncthreads();
#pragma unroll
        for (int kk = 0; kk < 16; kk++) {
            float a0 = Ss[(trow * 4 + 0) * 128 + kb * 16 + kk];
            float a1 = Ss[(trow * 4 + 1) * 128 + kb * 16 + kk];
            float a2 = Ss[(trow * 4 + 2) * 128 + kb * 16 + kk];
            float a3 = Ss[(trow * 4 + 3) * 128 + kb * 16 + kk];
            float4 b0 = *reinterpret_cast<const float4*>(&Ms[kk][tcol * 8]);
            float4 b1 = *reinterpret_cast<const float4*>(&Ms[kk][tcol * 8 + 4]);
            float b[8] = {b0.x, b0.y, b0.z, b0.w, b1.x, b1.y, b1.z, b1.w};
#pragma unroll
            for (int j = 0; j < 8; j++) {
                acc[0][j] += a0 * b[j];
                acc[1][j] += a1 * b[j];
                acc[2][j] += a2 * b[j];
                acc[3][j] += a3 * b[j];
            }
        }
    }

    float4 vb0 = *reinterpret_cast<const float4*>(&vb[tcol * 8]);
    float4 vb1 = *reinterpret_cast<const float4*>(&vb[tcol * 8 + 4]);
    float4 bo0 = *reinterpret_cast<const float4*>(&bo[tcol * 8]);
    float4 bo1 = *reinterpret_cast<const float4*>(&bo[tcol * 8 + 4]);
    float4 g0  = *reinterpret_cast<const float4*>(&lng[tcol * 8]);
    float4 g1  = *reinterpret_cast<const float4*>(&lng[tcol * 8 + 4]);
    float4 lb0 = *reinterpret_cast<const float4*>(&lnb[tcol * 8]);
    float4 lb1 = *reinterpret_cast<const float4*>(&lnb[tcol * 8 + 4]);
    float vbv[8] = {vb0.x, vb0.y, vb0.z, vb0.w, vb1.x, vb1.y, vb1.z, vb1.w};
    float bov[8] = {bo0.x, bo0.y, bo0.z, bo0.w, bo1.x, bo1.y, bo1.z, bo1.w};
    float gv[8]  = {g0.x, g0.y, g0.z, g0.w, g1.x, g1.y, g1.z, g1.w};
    float bvv[8] = {lb0.x, lb0.y, lb0.z, lb0.w, lb1.x, lb1.y, lb1.z, lb1.w};

#pragma unroll
    for (int i = 0; i < 4; i++) {
        int base = (trow * 4 + i) * 128;
        float deg = Ss[base] + Ss[base + 1] + Ss[base + 2] + Ss[base + 3];
        float v[8];
        float psum = 0.f;
#pragma unroll
        for (int j = 0; j < 8; j++) {
            v[j] = acc[i][j] + deg * vbv[j] + bov[j];
            psum += v[j];
        }
        float mean = warp_sum(psum) * (1.f / 256.f);
        float psq = 0.f;
#pragma unroll
        for (int j = 0; j < 8; j++) {
            float d = v[j] - mean;
            psq += d * d;
        }
        float var = warp_sum(psq) * (1.f / 256.f);
        float rs = rsqrtf(var + EPS_LN);

        int row = n0 + trow * 4 + i;
        float4 o0, o1;
        o0.x = (v[0] - mean) * rs * gv[0] + bvv[0];
        o0.y = (v[1] - mean) * rs * gv[1] + bvv[1];
        o0.z = (v[2] - mean) * rs * gv[2] + bvv[2];
        o0.w = (v[3] - mean) * rs * gv[3] + bvv[3];
        o1.x = (v[4] - mean) * rs * gv[4] + bvv[4];
        o1.y = (v[5] - mean) * rs * gv[5] + bvv[5];
        o1.z = (v[6] - mean) * rs * gv[6] + bvv[6];
        o1.w = (v[7] - mean) * rs * gv[7] + bvv[7];
        float* op = out + (size_t)row * 256 + tcol * 8;
        *reinterpret_cast<float4*>(op) = o0;
        *reinterpret_cast<float4*>(op + 4) = o1;
    }
}

// ---------------- launch ------------------------------------------------------
extern "C" void kernel_launch(void* const* d_in, const int* in_sizes, int n_in,
                              void* d_out, int out_size) {
    const float* x_a   = (const float*)d_in[0];
    const float* x_b   = (const float*)d_in[1];
    const int*   ei1   = (const int*)d_in[2];
    const float* ea1   = (const float*)d_in[3];
    const int*   ei2   = (const int*)d_in[4];
    const float* ea2   = (const float*)d_in[5];
    const float* Wn_a  = (const float*)d_in[6];
    const float* bn_a  = (const float*)d_in[7];
    const float* Wn_b  = (const float*)d_in[8];
    const float* bn_b  = (const float*)d_in[9];
    const float* We1   = (const float*)d_in[10];
    const float* be1   = (const float*)d_in[11];
    const float* Win1  = (const float*)d_in[12];
    const float* bin1  = (const float*)d_in[13];
    const float* Wout1 = (const float*)d_in[14];
    const float* bout1 = (const float*)d_in[15];
    const float* We2   = (const float*)d_in[16];
    const float* be2   = (const float*)d_in[17];
    const float* Win2  = (const float*)d_in[18];
    const float* bin2  = (const float*)d_in[19];
    const float* Wout2 = (const float*)d_in[20];
    const float* bout2 = (const float*)d_in[21];
    const float* Wo_a  = (const float*)d_in[22];
    const float* bo_a  = (const float*)d_in[23];
    const float* Wo_b  = (const float*)d_in[24];
    const float* bo_b  = (const float*)d_in[25];
    const float* ln_g  = (const float*)d_in[26];
    const float* ln_b  = (const float*)d_in[27];

    const int N = in_sizes[0] / 256;
    const int E = in_sizes[2] / 2;

    cudaFuncSetAttribute(gemm_mma, cudaFuncAttributeMaxDynamicSharedMemorySize, GEMM_SMEM);

    clear_S<<<2048, 256>>>();

    // bf16 hi/lo conversion of X
    {
        dim3 cg((NN * 256 / 4 + 255) / 256, 2);
        convert_X<<<cg, 256>>>(x_a, x_b);
    }

    // side a (from x_a): rows 0-255 = K1 map (Wk1 = Win1+64*64), rows 256-511 = Q2 map (Wq2 = Win2)
    combine_qk<<<512, 256>>>(0, Wn_a, bn_a, Win1 + 64 * 64, bin1 + 64, Win2, bin2);
    // side b (from x_b): rows 0-255 = Q1 map (Wq1 = Win1), rows 256-511 = K2 map (Wk2 = Win2+64*64)
    combine_qk<<<512, 256>>>(1, Wn_b, bn_b, Win1, bin1, Win2 + 64 * 64, bin2 + 64);
    compute_uw<<<1, 256>>>(0, Win1, bin1, We1, be1);
    compute_uw<<<1, 256>>>(1, Win2, bin2, We2, be2);
    compute_T<<<256, 256>>>(0, Wo_a, Wout2);
    compute_T<<<256, 256>>>(1, Wo_b, Wout1);
    compute_M2<<<128, 256>>>(0, Wo_a, bout2);
    compute_M2<<<128, 256>>>(1, Wo_b, bout1);

    // tensor-core QK projections (both sides): grid (nc, rowblocks, side)
    {
        dim3 gg(4, N / 128, 2);
        gemm_mma<<<gg, 256, GEMM_SMEM>>>();
    }

    // edge passes (attention + scatter)
    int eblocks = (E * 32 + 255) / 256;
    edge_kernel<<<eblocks, 256>>>(ei1, ea1, E, 0);   // -> g_Sb (out_b)
    edge_kernel<<<eblocks, 256>>>(ei2, ea2, E, 1);   // -> g_Sa (out_a)

    // fused node-level postprocess + LayerNorm
    post_kernel<<<N / 32, 256>>>(bo_a, ln_g, ln_b, (float*)d_out, 0, N);  // y_a
    post_kernel<<<N / 32, 256>>>(bo_b, ln_g, ln_b, (float*)d_out, 1, N);  // y_b
}

// round 17
// speedup vs baseline: 1.3143x; 1.2138x over previous
#include <cuda_runtime.h>
#include <cuda_bf16.h>
#include <cstdint>

// Problem constants (fixed by the dataset)
#define NN 65536
#define EE 131072
#define EPS_LN 1e-5f
#define SCALE_ATT 0.25f   // HD^-0.5, HD=16

// ---------------- scratch (device globals; no allocation allowed) ------------
__device__ __nv_bfloat16 g_QKa[(size_t)NN * 512];   // [K1 | Q2] from x_a (bf16)
__device__ __nv_bfloat16 g_QKb[(size_t)NN * 512];   // [Q1 | K2] from x_b (bf16)
__device__ float g_Sa[(size_t)NN * 128];    // scatter target for pass2 (out_a)
__device__ float g_Sb[(size_t)NN * 128];    // scatter target for pass1 (out_b)
__device__ __nv_bfloat16 g_Xh[(size_t)2 * NN * 256];  // bf16 of x_a|x_b
__device__ __nv_bfloat16 g_Mh[2 * 512 * 256];         // combined QK weights (bf16)
__device__ float g_bM[2 * 512];
__device__ float g_u1[4 * 64], g_w1[4 * 64];
__device__ float g_u2[4 * 64], g_w2[4 * 64];
__device__ float g_Ta[256 * 256], g_Tb[256 * 256];  // Wo @ BD(Wout)
__device__ float g_M2a[256 * 128], g_M2b[256 * 128];
__device__ float g_vba[256], g_vbb[256];

__device__ __forceinline__ uint32_t smem_to_u32(const void* p) {
    uint32_t a;
    asm("{ .reg .u64 t; cvta.to.shared.u64 t, %1; cvt.u32.u64 %0, t; }" : "=r"(a) : "l"(p));
    return a;
}

// ---------------- zero the scatter accumulators ------------------------------
__global__ void clear_S() {
    int i = blockIdx.x * blockDim.x + threadIdx.x;
    int stride = gridDim.x * blockDim.x;
    float4 z = make_float4(0.f, 0.f, 0.f, 0.f);
    float4* A = reinterpret_cast<float4*>(g_Sa);
    float4* B = reinterpret_cast<float4*>(g_Sb);
    const int total = NN * 128 / 4;
    for (int t = i; t < total; t += stride) { A[t] = z; B[t] = z; }
}

// ---------------- convert X to bf16 ------------------------------------------
__global__ void convert_X(const float* __restrict__ xa, const float* __restrict__ xb) {
    int side = blockIdx.y;
    const float* X = side ? xb : xa;
    size_t i = (size_t)blockIdx.x * blockDim.x + threadIdx.x;  // group of 4 floats
    const size_t total = (size_t)NN * 256 / 4;
    if (i >= total) return;
    float4 v = reinterpret_cast<const float4*>(X)[i];
    __nv_bfloat162* H = reinterpret_cast<__nv_bfloat162*>(g_Xh + (size_t)side * NN * 256);
    H[i * 2]     = __floats2bfloat162_rn(v.x, v.y);
    H[i * 2 + 1] = __floats2bfloat162_rn(v.z, v.w);
}

// ---------------- combined QK weight precompute (bf16 output) ----------------
__global__ void combine_qk(int side,
                           const float* __restrict__ Wn, const float* __restrict__ bn,
                           const float* __restrict__ Wf, const float* __restrict__ bf,
                           const float* __restrict__ Ws, const float* __restrict__ bs) {
    __nv_bfloat16* Mh = g_Mh + side * 512 * 256;
    float* bias = g_bM + side * 512;
    int idx = blockIdx.x * blockDim.x + threadIdx.x;  // 512*256 threads
    int jout = idx >> 8;        // 0..511
    int c    = idx & 255;
    int hsel = jout >> 8;
    int jo   = jout & 255;
    int g = jo >> 6, j = jo & 63;
    const float* Wsub = hsel ? Ws : Wf;
    float acc = 0.f;
#pragma unroll 8
    for (int d = 0; d < 64; d++)
        acc += Wsub[j * 64 + d] * Wn[(g * 64 + d) * 256 + c];
    Mh[jout * 256 + c] = __float2bfloat16(acc);
    if (c == 0) {
        const float* bsub = hsel ? bs : bf;
        float bacc = bsub[j];
#pragma unroll 8
        for (int d = 0; d < 64; d++) bacc += Wsub[j * 64 + d] * bn[g * 64 + d];
        bias[jout] = bacc;
    }
}

// ---------------- u/w precompute ---------------------------------------------
__global__ void compute_uw(int pass, const float* __restrict__ Win,
                           const float* __restrict__ bin,
                           const float* __restrict__ We, const float* __restrict__ be) {
    float* u = pass ? g_u2 : g_u1;
    float* w = pass ? g_w2 : g_w1;
    int t = threadIdx.x;
    int ki = t >> 6, j = t & 63;
    const float* Wv = Win + 128 * 64;
    float su = 0.f, sw = 0.f;
#pragma unroll 8
    for (int d = 0; d < 64; d++) {
        float wv = Wv[j * 64 + d];
        su += wv * We[ki * 64 + d];
        sw += wv * be[ki * 64 + d];
    }
    u[t] = su;
    w[t] = sw + bin[128 + j];
}

// ---------------- T = Wo @ BD(Wout) ------------------------------------------
__global__ void compute_T(int side, const float* __restrict__ Wo,
                          const float* __restrict__ Wout) {
    float* T = side ? g_Tb : g_Ta;
    int idx = blockIdx.x * 256 + threadIdx.x;
    int r = idx >> 8, qo = idx & 255;
    int qi = qo >> 6, j = qo & 63;
    float acc = 0.f;
#pragma unroll 8
    for (int jj = 0; jj < 64; jj++)
        acc += Wo[r * 256 + qi * 64 + jj] * Wout[jj * 64 + j];
    T[idx] = acc;
}

// ---------------- M2 = T @ G(u,w) --------------------------------------------
__global__ void compute_M2(int side, const float* __restrict__ Wo,
                           const float* __restrict__ bout) {
    const float* T = side ? g_Tb : g_Ta;
    const float* u = side ? g_u1 : g_u2;
    const float* w = side ? g_w1 : g_w2;
    float* M2 = side ? g_M2b : g_M2a;
    float* vb = side ? g_vbb : g_vba;
    int idx = blockIdx.x * 256 + threadIdx.x;
    int r = idx >> 7, s = idx & 127;
    int z = s >> 6;
    int rest = s & 63;
    int h = rest >> 4, qr = (rest >> 2) & 3, ki = rest & 3;
    const float* coef = z ? u : w;
    float acc = 0.f;
#pragma unroll
    for (int hd = 0; hd < 16; hd++)
        acc += T[r * 256 + qr * 64 + h * 16 + hd] * coef[ki * 64 + h * 16 + hd];
    M2[r * 128 + s] = acc;
    if (s == 0) {
        float b = 0.f;
        for (int qi2 = 0; qi2 < 4; qi2++)
#pragma unroll 8
            for (int jj = 0; jj < 64; jj++)
                b += Wo[r * 256 + qi2 * 64 + jj] * bout[jj];
        vb[r] = b;
    }
}

// ---------------- mma.sync QK GEMM (single-term bf16) ------------------------
// out[N,512](bf16) = X[N,256] @ M^T + bias, bf16 inputs, fp32 accum.
// Block: 256 threads (8 warps, 4m x 2n), tile 128M x 128N, K in 4 chunks of 64.
// SMEM 36KB -> 2 CTAs/SM; co-resident CTAs overlap load/compute phases.
// grid: (4 nc, N/128 rows, 2 sides) — nc fastest for L2 reuse of A.
#define SROW 72   // padded bf16 stride in smem (144B rows -> conflict-free)
#define GEMM_SMEM (2 * 128 * SROW * 2)   // 36864 B

#define LDSM_X4(r, addr) \
    asm volatile("ldmatrix.sync.aligned.m8n8.x4.shared.b16 {%0,%1,%2,%3}, [%4];" \
        : "=r"((r)[0]), "=r"((r)[1]), "=r"((r)[2]), "=r"((r)[3]) : "r"(addr))
#define LDSM_X2(r, addr) \
    asm volatile("ldmatrix.sync.aligned.m8n8.x2.shared.b16 {%0,%1}, [%2];" \
        : "=r"((r)[0]), "=r"((r)[1]) : "r"(addr))
#define MMA16816(c, a, b) \
    asm volatile("mma.sync.aligned.m16n8k16.row.col.f32.bf16.bf16.f32 " \
        "{%0,%1,%2,%3}, {%4,%5,%6,%7}, {%8,%9}, {%0,%1,%2,%3};" \
        : "+f"((c)[0]), "+f"((c)[1]), "+f"((c)[2]), "+f"((c)[3]) \
        : "r"((a)[0]), "r"((a)[1]), "r"((a)[2]), "r"((a)[3]), "r"((b)[0]), "r"((b)[1]))

__global__ void __launch_bounds__(256, 2) gemm_mma() {
    extern __shared__ __nv_bfloat16 sm[];
    __nv_bfloat16* sA = sm;                 // 128*72
    __nv_bfloat16* sB = sm + 128 * SROW;

    int nc   = blockIdx.x;      // 0..3 : output col block of 128
    int rb   = blockIdx.y;      // row block of 128
    int side = blockIdx.z;
    int tid = threadIdx.x, wid = tid >> 5, lane = tid & 31;
    int wm = wid & 3, wn = wid >> 2;

    const __nv_bfloat16* Ag = g_Xh + (size_t)side * NN * 256 + (size_t)rb * 128 * 256;
    const __nv_bfloat16* Bg = g_Mh + side * 512 * 256 + nc * 128 * 256;

    float c[2][8][4];
#pragma unroll
    for (int mt = 0; mt < 2; mt++)
#pragma unroll
        for (int nt = 0; nt < 8; nt++)
#pragma unroll
            for (int q = 0; q < 4; q++) c[mt][nt][q] = 0.f;

    uint32_t sb = smem_to_u32(sm);
    const uint32_t offB = 128 * SROW * 2;   // bytes

    for (int kc = 0; kc < 4; kc++) {
        __syncthreads();
        // load chunk: A/B, 128 rows x 64 cols each
#pragma unroll
        for (int i = 0; i < 4; i++) {
            int idx = tid + i * 256;                // [0,1024)
            int row = idx >> 3, cg = idx & 7;
            size_t goff = (size_t)row * 256 + kc * 64 + cg * 8;
            int soff = row * SROW + cg * 8;
            *reinterpret_cast<uint4*>(sA + soff) = *reinterpret_cast<const uint4*>(Ag + goff);
            *reinterpret_cast<uint4*>(sB + soff) = *reinterpret_cast<const uint4*>(Bg + goff);
        }
        __syncthreads();

#pragma unroll
        for (int ks = 0; ks < 4; ks++) {
            int k0 = ks * 16;
            uint32_t ah[2][4], bh[8][2];
#pragma unroll
            for (int mt = 0; mt < 2; mt++) {
                int r = wm * 32 + mt * 16 + (lane & 15);
                uint32_t addr = sb + (uint32_t)(r * SROW + k0 + (lane >> 4) * 8) * 2;
                LDSM_X4(ah[mt], addr);
            }
#pragma unroll
            for (int nt = 0; nt < 8; nt++) {
                int n = wn * 64 + nt * 8 + (lane & 7);
                uint32_t addr = sb + offB + (uint32_t)(n * SROW + k0 + ((lane >> 3) & 1) * 8) * 2;
                LDSM_X2(bh[nt], addr);
            }
#pragma unroll
            for (int mt = 0; mt < 2; mt++)
#pragma unroll
                for (int nt = 0; nt < 8; nt++)
                    MMA16816(c[mt][nt], ah[mt], bh[nt]);
        }
    }

    // epilogue: add bias, store bf16
    const float* bias = g_bM + side * 512;
    __nv_bfloat16* out = side ? g_QKb : g_QKa;
    int col0 = nc * 128 + wn * 64;
#pragma unroll
    for (int mt = 0; mt < 2; mt++) {
        int r0 = rb * 128 + wm * 32 + mt * 16 + (lane >> 2);
#pragma unroll
        for (int nt = 0; nt < 8; nt++) {
            int cb = col0 + nt * 8 + (lane & 3) * 2;
            float2 bv = *reinterpret_cast<const float2*>(bias + cb);
            __nv_bfloat162 p0 = __floats2bfloat162_rn(c[mt][nt][0] + bv.x, c[mt][nt][1] + bv.y);
            __nv_bfloat162 p1 = __floats2bfloat162_rn(c[mt][nt][2] + bv.x, c[mt][nt][3] + bv.y);
            *reinterpret_cast<__nv_bfloat162*>(out + (size_t)r0 * 512 + cb) = p0;
            *reinterpret_cast<__nv_bfloat162*>(out + (size_t)(r0 + 8) * 512 + cb) = p1;
        }
    }
}

// ---------------- edge kernel: attention weights + S0/S1 scatter -------------
// one warp per edge; lane layout: pair = lane&15 -> (h, qi); half = lane>>4 -> ki pair
__global__ void __launch_bounds__(256) edge_kernel(const int* __restrict__ ei,
                                                   const float* __restrict__ ea,
                                                   int E, int pass) {
    int gid = blockIdx.x * blockDim.x + threadIdx.x;
    int e = gid >> 5;
    int lane = gid & 31;
    if (e >= E) return;

    const __nv_bfloat16* Q;
    const __nv_bfloat16* K;
    float* S;
    if (pass == 0) { Q = g_QKb;       K = g_QKa;       S = g_Sb; }
    else           { Q = g_QKa + 256; K = g_QKb + 256; S = g_Sa; }

    int src = ei[e];
    int dst = ei[E + e];
    float eav = ea[e];

    int pair = lane & 15;
    int h = pair >> 2;
    int qi = pair & 3;
    int half = lane >> 4;
    int ki0 = half * 2;

    // 16 bf16 (32B) per operand, loaded as 2 x uint4
    const uint4* qp  = reinterpret_cast<const uint4*>(Q + (size_t)dst * 512 + qi * 64 + h * 16);
    const uint4* kp0 = reinterpret_cast<const uint4*>(K + (size_t)src * 512 + ki0 * 64 + h * 16);
    const uint4* kp1 = reinterpret_cast<const uint4*>(K + (size_t)src * 512 + (ki0 + 1) * 64 + h * 16);

    uint4 qv[2]  = {qp[0], qp[1]};
    uint4 k0v[2] = {kp0[0], kp0[1]};
    uint4 k1v[2] = {kp1[0], kp1[1]};
    const __nv_bfloat162* q2 = reinterpret_cast<const __nv_bfloat162*>(qv);
    const __nv_bfloat162* a2 = reinterpret_cast<const __nv_bfloat162*>(k0v);
    const __nv_bfloat162* b2 = reinterpret_cast<const __nv_bfloat162*>(k1v);

    float s0 = 0.f, s1 = 0.f;
#pragma unroll
    for (int t = 0; t < 8; t++) {
        float2 qf = __bfloat1622float2(q2[t]);
        float2 ka = __bfloat1622float2(a2[t]);
        float2 kb = __bfloat1622float2(b2[t]);
        s0 += qf.x * ka.x + qf.y * ka.y;
        s1 += qf.x * kb.x + qf.y * kb.y;
    }
    s0 *= SCALE_ATT;
    s1 *= SCALE_ATT;

    float o0 = __shfl_xor_sync(0xffffffffu, s0, 16);
    float o1 = __shfl_xor_sync(0xffffffffu, s1, 16);
    float mx = fmaxf(fmaxf(s0, s1), fmaxf(o0, o1));
    float e0  = __expf(s0 - mx), e1  = __expf(s1 - mx);
    float eo0 = __expf(o0 - mx), eo1 = __expf(o1 - mx);
    float inv = 1.f / (e0 + e1 + eo0 + eo1);
    float a0 = e0 * inv, a1 = e1 * inv;

    float* Sp = S + (size_t)dst * 128 + h * 16 + qi * 4;
    atomicAdd(Sp + ki0,          a0);
    atomicAdd(Sp + ki0 + 1,      a1);
    atomicAdd(Sp + 64 + ki0,     eav * a0);
    atomicAdd(Sp + 64 + ki0 + 1, eav * a1);
}

// ---------------- warp all-reduce -------------------------------------------
__device__ __forceinline__ float warp_sum(float x) {
    x += __shfl_xor_sync(0xffffffffu, x, 16);
    x += __shfl_xor_sync(0xffffffffu, x, 8);
    x += __shfl_xor_sync(0xffffffffu, x, 4);
    x += __shfl_xor_sync(0xffffffffu, x, 2);
    x += __shfl_xor_sync(0xffffffffu, x, 1);
    return x;
}

// ---------------- post kernel: y = LN(S @ M2^T + deg*vb + bo) ----------------
__global__ void __launch_bounds__(256) post_kernel(const float* __restrict__ bo,
                                                   const float* __restrict__ lng,
                                                   const float* __restrict__ lnb,
                                                   float* __restrict__ outbase,
                                                   int side, int Nn) {
    const float* S  = side ? g_Sb  : g_Sa;
    const float* M2 = side ? g_M2b : g_M2a;
    const float* vb = side ? g_vbb : g_vba;
    float* out = outbase + (size_t)side * Nn * 256;

    __shared__ float Ss[32 * 128];
    __shared__ float Ms[16][256];

    int tid = threadIdx.x;
    int n0 = blockIdx.x * 32;

    {
        const float4* Sg = reinterpret_cast<const float4*>(S + (size_t)n0 * 128);
        float4* Sd = reinterpret_cast<float4*>(Ss);
#pragma unroll
        for (int i = 0; i < 4; i++) Sd[tid + i * 256] = Sg[tid + i * 256];
    }

    int trow = tid >> 5, tcol = tid & 31;
    float acc[4][8];
#pragma unroll
    for (int i = 0; i < 4; i++)
#pragma unroll
        for (int j = 0; j < 8; j++) acc[i][j] = 0.f;

    for (int kb = 0; kb < 8; kb++) {
        __syncthreads();
        {
            const float4* m4 = reinterpret_cast<const float4*>(M2 + (size_t)tid * 128 + kb * 16);
            float4 v0 = m4[0], v1 = m4[1], v2 = m4[2], v3 = m4[3];
            Ms[0][tid] = v0.x;  Ms[1][tid] = v0.y;  Ms[2][tid] = v0.z;  Ms[3][tid] = v0.w;
            Ms[4][tid] = v1.x;  Ms[5][tid] = v1.y;  Ms[6][tid] = v1.z;  Ms[7][tid] = v1.w;
            Ms[8][tid] = v2.x;  Ms[9][tid] = v2.y;  Ms[10][tid] = v2.z; Ms[11][tid] = v2.w;
            Ms[12][tid] = v3.x; Ms[13][tid] = v3.y; Ms[14][tid] = v3.z; Ms[15][tid] = v3.w;
        }
        __syncthreads();
#pragma unroll
        for (int kk = 0; kk < 16; kk++) {
            float a0 = Ss[(trow * 4 + 0) * 128 + kb * 16 + kk];
            float a1 = Ss[(trow * 4 + 1) * 128 + kb * 16 + kk];
            float a2 = Ss[(trow * 4 + 2) * 128 + kb * 16 + kk];
            float a3 = Ss[(trow * 4 + 3) * 128 + kb * 16 + kk];
            float4 b0 = *reinterpret_cast<const float4*>(&Ms[kk][tcol * 8]);
            float4 b1 = *reinterpret_cast<const float4*>(&Ms[kk][tcol * 8 + 4]);
            float b[8] = {b0.x, b0.y, b0.z, b0.w, b1.x, b1.y, b1.z, b1.w};
#pragma unroll
            for (int j = 0; j < 8; j++) {
                acc[0][j] += a0 * b[j];
                acc[1][j] += a1 * b[j];
                acc[2][j] += a2 * b[j];
                acc[3][j] += a3 * b[j];
            }
        }
    }

    float4 vb0 = *reinterpret_cast<const float4*>(&vb[tcol * 8]);
    float4 vb1 = *reinterpret_cast<const float4*>(&vb[tcol * 8 + 4]);
    float4 bo0 = *reinterpret_cast<const float4*>(&bo[tcol * 8]);
    float4 bo1 = *reinterpret_cast<const float4*>(&bo[tcol * 8 + 4]);
    float4 g0  = *reinterpret_cast<const float4*>(&lng[tcol * 8]);
    float4 g1  = *reinterpret_cast<const float4*>(&lng[tcol * 8 + 4]);
    float4 lb0 = *reinterpret_cast<const float4*>(&lnb[tcol * 8]);
    float4 lb1 = *reinterpret_cast<const float4*>(&lnb[tcol * 8 + 4]);
    float vbv[8] = {vb0.x, vb0.y, vb0.z, vb0.w, vb1.x, vb1.y, vb1.z, vb1.w};
    float bov[8] = {bo0.x, bo0.y, bo0.z, bo0.w, bo1.x, bo1.y, bo1.z, bo1.w};
    float gv[8]  = {g0.x, g0.y, g0.z, g0.w, g1.x, g1.y, g1.z, g1.w};
    float bvv[8] = {lb0.x, lb0.y, lb0.z, lb0.w, lb1.x, lb1.y, lb1.z, lb1.w};

#pragma unroll
    for (int i = 0; i < 4; i++) {
        int base = (trow * 4 + i) * 128;
        float deg = Ss[base] + Ss[base + 1] + Ss[base + 2] + Ss[base + 3];
        float v[8];
        float psum = 0.f;
#pragma unroll
        for (int j = 0; j < 8; j++) {
            v[j] = acc[i][j] + deg * vbv[j] + bov[j];
            psum += v[j];
        }
        float mean = warp_sum(psum) * (1.f / 256.f);
        float psq = 0.f;
#pragma unroll
        for (int j = 0; j < 8; j++) {
            float d = v[j] - mean;
            psq += d * d;
        }
        float var = warp_sum(psq) * (1.f / 256.f);
        float rs = rsqrtf(var + EPS_LN);

        int row = n0 + trow * 4 + i;
        float4 o0, o1;
        o0.x = (v[0] - mean) * rs * gv[0] + bvv[0];
        o0.y = (v[1] - mean) * rs * gv[1] + bvv[1];
        o0.z = (v[2] - mean) * rs * gv[2] + bvv[2];
        o0.w = (v[3] - mean) * rs * gv[3] + bvv[3];
        o1.x = (v[4] - mean) * rs * gv[4] + bvv[4];
        o1.y = (v[5] - mean) * rs * gv[5] + bvv[5];
        o1.z = (v[6] - mean) * rs * gv[6] + bvv[6];
        o1.w = (v[7] - mean) * rs * gv[7] + bvv[7];
        float* op = out + (size_t)row * 256 + tcol * 8;
        *reinterpret_cast<float4*>(op) = o0;
        *reinterpret_cast<float4*>(op + 4) = o1;
    }
}

// ---------------- launch ------------------------------------------------------
extern "C" void kernel_launch(void* const* d_in, const int* in_sizes, int n_in,
                              void* d_out, int out_size) {
    const float* x_a   = (const float*)d_in[0];
    const float* x_b   = (const float*)d_in[1];
    const int*   ei1   = (const int*)d_in[2];
    const float* ea1   = (const float*)d_in[3];
    const int*   ei2   = (const int*)d_in[4];
    const float* ea2   = (const float*)d_in[5];
    const float* Wn_a  = (const float*)d_in[6];
    const float* bn_a  = (const float*)d_in[7];
    const float* Wn_b  = (const float*)d_in[8];
    const float* bn_b  = (const float*)d_in[9];
    const float* We1   = (const float*)d_in[10];
    const float* be1   = (const float*)d_in[11];
    const float* Win1  = (const float*)d_in[12];
    const float* bin1  = (const float*)d_in[13];
    const float* Wout1 = (const float*)d_in[14];
    const float* bout1 = (const float*)d_in[15];
    const float* We2   = (const float*)d_in[16];
    const float* be2   = (const float*)d_in[17];
    const float* Win2  = (const float*)d_in[18];
    const float* bin2  = (const float*)d_in[19];
    const float* Wout2 = (const float*)d_in[20];
    const float* bout2 = (const float*)d_in[21];
    const float* Wo_a  = (const float*)d_in[22];
    const float* bo_a  = (const float*)d_in[23];
    const float* Wo_b  = (const float*)d_in[24];
    const float* bo_b  = (const float*)d_in[25];
    const float* ln_g  = (const float*)d_in[26];
    const float* ln_b  = (const float*)d_in[27];

    const int N = in_sizes[0] / 256;
    const int E = in_sizes[2] / 2;

    cudaFuncSetAttribute(gemm_mma, cudaFuncAttributeMaxDynamicSharedMemorySize, GEMM_SMEM);

    clear_S<<<2048, 256>>>();

    // bf16 conversion of X
    {
        dim3 cg((NN * 256 / 4 + 255) / 256, 2);
        convert_X<<<cg, 256>>>(x_a, x_b);
    }

    // side a (from x_a): rows 0-255 = K1 map (Wk1 = Win1+64*64), rows 256-511 = Q2 map (Wq2 = Win2)
    combine_qk<<<512, 256>>>(0, Wn_a, bn_a, Win1 + 64 * 64, bin1 + 64, Win2, bin2);
    // side b (from x_b): rows 0-255 = Q1 map (Wq1 = Win1), rows 256-511 = K2 map (Wk2 = Win2+64*64)
    combine_qk<<<512, 256>>>(1, Wn_b, bn_b, Win1, bin1, Win2 + 64 * 64, bin2 + 64);
    compute_uw<<<1, 256>>>(0, Win1, bin1, We1, be1);
    compute_uw<<<1, 256>>>(1, Win2, bin2, We2, be2);
    compute_T<<<256, 256>>>(0, Wo_a, Wout2);
    compute_T<<<256, 256>>>(1, Wo_b, Wout1);
    compute_M2<<<128, 256>>>(0, Wo_a, bout2);
    compute_M2<<<128, 256>>>(1, Wo_b, bout1);

    // tensor-core QK projections (both sides): grid (nc, rowblocks, side)
    {
        dim3 gg(4, N / 128, 2);
        gemm_mma<<<gg, 256, GEMM_SMEM>>>();
    }

    // edge passes (attention + scatter)
    int eblocks = (E * 32 + 255) / 256;
    edge_kernel<<<eblocks, 256>>>(ei1, ea1, E, 0);   // -> g_Sb (out_b)
    edge_kernel<<<eblocks, 256>>>(ei2, ea2, E, 1);   // -> g_Sa (out_a)

    // fused node-level postprocess + LayerNorm
    post_kernel<<<N / 32, 256>>>(bo_a, ln_g, ln_b, (float*)d_out, 0, N);  // y_a
    post_kernel<<<N / 32, 256>>>(bo_b, ln_g, ln_b, (float*)d_out, 1, N);  // y_b
}